// round 5
// baseline (speedup 1.0000x reference)
#include <cuda_runtime.h>
#include <cstdint>

// DetectionLayer: x (16, 255, 76, 76) f32 -> out (16, 17328, 85) f32
// out[b, a*5776 + gy*76 + gx, c]:
//   c==0: (sigmoid(x0)+gx)*8 ; c==1: (sigmoid(x1)+gy)*8
//   c==2: exp(x2)*aw[a]      ; c==3: exp(x3)*ah[a]
//   c>=4: sigmoid(xc)
// x_c = x[b, a*85+c, gy, gx]; stride = 608/76 = 8.
// sigmoid(v) = 0.5 + 0.5*tanh(v/2)  (tanh.approx.f32: 1 MUFU instead of 2)

#define NG    76
#define NGG   (NG * NG)     // 5776
#define NGV   19            // float4s per grid row
#define NA    3
#define NCH   85
#define TILE_F (NG * NCH)   // 6460 floats = block's contiguous output chunk
#define NVEC  (TILE_F / 4)  // 1615 float4s

__device__ __forceinline__ float tanh_half(float v) {
    float t;
    asm("tanh.approx.f32 %0, %1;" : "=f"(t) : "f"(v * 0.5f));
    return t;  // tanh(v/2); sigmoid(v) = fmaf(t, 0.5f, 0.5f)
}

__device__ __forceinline__ void xform_store(
    float4 in, int c, int g, float aw, float ah, float fgy,
    float* __restrict__ tile)
{
    float4 o;
    if (c >= 4) {
        o.x = fmaf(tanh_half(in.x), 0.5f, 0.5f);
        o.y = fmaf(tanh_half(in.y), 0.5f, 0.5f);
        o.z = fmaf(tanh_half(in.z), 0.5f, 0.5f);
        o.w = fmaf(tanh_half(in.w), 0.5f, 0.5f);
    } else if (c == 0) {
        // (sig + gx)*8 = 4*t + 4 + 8*gx
        const float base = fmaf((float)(g << 2), 8.0f, 4.0f);
        o.x = fmaf(tanh_half(in.x), 4.0f, base);
        o.y = fmaf(tanh_half(in.y), 4.0f, base + 8.0f);
        o.z = fmaf(tanh_half(in.z), 4.0f, base + 16.0f);
        o.w = fmaf(tanh_half(in.w), 4.0f, base + 24.0f);
    } else if (c == 1) {
        const float base = fmaf(fgy, 8.0f, 4.0f);
        o.x = fmaf(tanh_half(in.x), 4.0f, base);
        o.y = fmaf(tanh_half(in.y), 4.0f, base);
        o.z = fmaf(tanh_half(in.z), 4.0f, base);
        o.w = fmaf(tanh_half(in.w), 4.0f, base);
    } else {
        const float an = (c == 2) ? aw : ah;
        o.x = __expf(in.x) * an; o.y = __expf(in.y) * an;
        o.z = __expf(in.z) * an; o.w = __expf(in.w) * an;
    }
    // scatter into output-layout tile: tile[(4g+k)*85 + c]
    float* t = &tile[(g << 2) * NCH + c];
    t[0]       = o.x;
    t[NCH]     = o.y;
    t[2 * NCH] = o.z;
    t[3 * NCH] = o.w;
}

__global__ __launch_bounds__(256)
void detection_layer_kernel(const float* __restrict__ x, float* __restrict__ out) {
    const int tid = threadIdx.x;
    const int gy = blockIdx.x;   // 0..75
    const int a  = blockIdx.y;   // 0..2
    const int b  = blockIdx.z;   // 0..15

    // smem tile holds the output chunk in FINAL layout: tile[s*85 + c]
    __shared__ float tile[TILE_F];

    const float aw = (a == 0) ? 10.0f : (a == 1 ? 16.0f : 33.0f);
    const float ah = (a == 0) ? 13.0f : (a == 1 ? 30.0f : 23.0f);
    const float fgy = (float)gy;

    // input base for (b, a*85 + 0, gy, 0): multiple of 76 floats -> 16B aligned
    const float* src = x + ((size_t)(b * (NA * NCH) + a * NCH) * NG + gy) * NG;

    // ---- Phase 1: paired coalesced loads, transform, scatter to smem ----
    // 1615 = 3*512 + 79 : three paired rounds + tail.
    #pragma unroll 1
    for (int base = 0; base < 1536; base += 512) {
        const int v0 = base + tid;
        const int v1 = v0 + 256;
        const int c0 = v0 / NGV, g0 = v0 - c0 * NGV;
        const int c1 = v1 / NGV, g1 = v1 - c1 * NGV;
        const float4 a0 = *reinterpret_cast<const float4*>(
            src + (size_t)c0 * NGG + (g0 << 2));
        const float4 a1 = *reinterpret_cast<const float4*>(
            src + (size_t)c1 * NGG + (g1 << 2));
        xform_store(a0, c0, g0, aw, ah, fgy, tile);
        xform_store(a1, c1, g1, aw, ah, fgy, tile);
    }
    {
        const int v = 1536 + tid;
        if (v < NVEC) {
            const int c = v / NGV, g = v - c * NGV;
            const float4 a0 = *reinterpret_cast<const float4*>(
                src + (size_t)c * NGG + (g << 2));
            xform_store(a0, c, g, aw, ah, fgy, tile);
        }
    }
    __syncthreads();

    // ---- Phase 2: vector copy smem -> gmem, unrolled x3 ----
    float* dst = out + ((size_t)b * (NA * NGG) + a * NGG + gy * NG) * (size_t)NCH;
    float4* __restrict__ dst4 = reinterpret_cast<float4*>(dst);
    const float4* __restrict__ s4 = reinterpret_cast<const float4*>(tile);
    #pragma unroll 1
    for (int base = 0; base < 1536; base += 768) {
        const int i0 = base + tid;
        const float4 q0 = s4[i0];
        const float4 q1 = s4[i0 + 256];
        const float4 q2 = s4[i0 + 512];
        dst4[i0]       = q0;
        dst4[i0 + 256] = q1;
        dst4[i0 + 512] = q2;
    }
    {
        const int i = 1536 + tid;
        if (i < NVEC) dst4[i] = s4[i];
    }
}

extern "C" void kernel_launch(void* const* d_in, const int* in_sizes, int n_in,
                              void* d_out, int out_size) {
    const float* x = (const float*)d_in[0];
    float* out = (float*)d_out;
    dim3 grid(NG, NA, 16);
    detection_layer_kernel<<<grid, 256>>>(x, out);
}

// round 6
// speedup vs baseline: 1.0913x; 1.0913x over previous
#include <cuda_runtime.h>
#include <cstdint>

// DetectionLayer: x (16, 255, 76, 76) f32 -> out (16, 17328, 85) f32
// out[b, a*5776 + gy*76 + gx, c]:
//   c==0: (sigmoid(x0)+gx)*8 ; c==1: (sigmoid(x1)+gy)*8
//   c==2: exp(x2)*aw[a]      ; c==3: exp(x3)*ah[a]
//   c>=4: sigmoid(xc)
// sigmoid(v) = 0.5 + 0.5*tanh(v/2) (1 MUFU). Phase 2 = TMA bulk store.

#define NG    76
#define NGG   (NG * NG)     // 5776
#define NGV   19            // float4s per grid row
#define NA    3
#define NCH   85
#define TILE_F (NG * NCH)   // 6460 floats = block's contiguous output chunk
#define TILE_B (TILE_F * 4) // 25840 bytes (multiple of 16)
#define NVEC  (TILE_F / 4)  // 1615 float4s

__device__ __forceinline__ float tanh_half(float v) {
    float t;
    asm("tanh.approx.f32 %0, %1;" : "=f"(t) : "f"(v * 0.5f));
    return t;  // tanh(v/2); sigmoid(v) = fmaf(t, 0.5f, 0.5f)
}

__device__ __forceinline__ void xform_store(
    float4 in, int c, int g, float aw, float ah, float fgy,
    float* __restrict__ tile)
{
    float4 o;
    if (c >= 4) {
        o.x = fmaf(tanh_half(in.x), 0.5f, 0.5f);
        o.y = fmaf(tanh_half(in.y), 0.5f, 0.5f);
        o.z = fmaf(tanh_half(in.z), 0.5f, 0.5f);
        o.w = fmaf(tanh_half(in.w), 0.5f, 0.5f);
    } else if (c == 0) {
        // (sig + gx)*8 = 4*t + 4 + 8*gx
        const float base = fmaf((float)(g << 2), 8.0f, 4.0f);
        o.x = fmaf(tanh_half(in.x), 4.0f, base);
        o.y = fmaf(tanh_half(in.y), 4.0f, base + 8.0f);
        o.z = fmaf(tanh_half(in.z), 4.0f, base + 16.0f);
        o.w = fmaf(tanh_half(in.w), 4.0f, base + 24.0f);
    } else if (c == 1) {
        const float base = fmaf(fgy, 8.0f, 4.0f);
        o.x = fmaf(tanh_half(in.x), 4.0f, base);
        o.y = fmaf(tanh_half(in.y), 4.0f, base);
        o.z = fmaf(tanh_half(in.z), 4.0f, base);
        o.w = fmaf(tanh_half(in.w), 4.0f, base);
    } else {
        const float an = (c == 2) ? aw : ah;
        o.x = __expf(in.x) * an; o.y = __expf(in.y) * an;
        o.z = __expf(in.z) * an; o.w = __expf(in.w) * an;
    }
    // scatter into output-layout tile: tile[(4g+k)*85 + c]
    float* t = &tile[(g << 2) * NCH + c];
    t[0]       = o.x;
    t[NCH]     = o.y;
    t[2 * NCH] = o.z;
    t[3 * NCH] = o.w;
}

__global__ __launch_bounds__(256)
void detection_layer_kernel(const float* __restrict__ x, float* __restrict__ out) {
    const int tid = threadIdx.x;
    const int gy = blockIdx.x;   // 0..75
    const int a  = blockIdx.y;   // 0..2
    const int b  = blockIdx.z;   // 0..15

    // smem tile holds the output chunk in FINAL layout: tile[s*85 + c]
    __shared__ __align__(16) float tile[TILE_F];

    const float aw = (a == 0) ? 10.0f : (a == 1 ? 16.0f : 33.0f);
    const float ah = (a == 0) ? 13.0f : (a == 1 ? 30.0f : 23.0f);
    const float fgy = (float)gy;

    // input base for (b, a*85 + 0, gy, 0): multiple of 76 floats -> 16B aligned
    const float* src = x + ((size_t)(b * (NA * NCH) + a * NCH) * NG + gy) * NG;

    // ---- Phase 1: paired coalesced loads, transform, scatter to smem ----
    // 1615 = 3*512 + 79 : three paired rounds + tail.
    #pragma unroll 1
    for (int base = 0; base < 1536; base += 512) {
        const int v0 = base + tid;
        const int v1 = v0 + 256;
        const int c0 = v0 / NGV, g0 = v0 - c0 * NGV;
        const int c1 = v1 / NGV, g1 = v1 - c1 * NGV;
        const float4 a0 = *reinterpret_cast<const float4*>(
            src + (size_t)c0 * NGG + (g0 << 2));
        const float4 a1 = *reinterpret_cast<const float4*>(
            src + (size_t)c1 * NGG + (g1 << 2));
        xform_store(a0, c0, g0, aw, ah, fgy, tile);
        xform_store(a1, c1, g1, aw, ah, fgy, tile);
    }
    {
        const int v = 1536 + tid;
        if (v < NVEC) {
            const int c = v / NGV, g = v - c * NGV;
            const float4 a0 = *reinterpret_cast<const float4*>(
                src + (size_t)c * NGG + (g << 2));
            xform_store(a0, c, g, aw, ah, fgy, tile);
        }
    }
    __syncthreads();

    // ---- Phase 2: single TMA bulk store smem -> gmem (25840 B) ----
    if (tid == 0) {
        // order generic-proxy STS before async-proxy TMA reads
        asm volatile("fence.proxy.async.shared::cta;" ::: "memory");

        uint32_t saddr;
        asm("{ .reg .u64 t; cvta.to.shared.u64 t, %1; cvt.u32.u64 %0, t; }"
            : "=r"(saddr) : "l"(tile));

        float* dst = out +
            ((size_t)b * (NA * NGG) + a * NGG + gy * NG) * (size_t)NCH;

        asm volatile(
            "cp.async.bulk.global.shared::cta.bulk_group [%0], [%1], %2;"
            :: "l"(dst), "r"(saddr), "r"((uint32_t)TILE_B) : "memory");
        asm volatile("cp.async.bulk.commit_group;" ::: "memory");
        // keep CTA (and its smem) alive until the engine has read the tile;
        // write visibility is guaranteed at kernel completion.
        asm volatile("cp.async.bulk.wait_group.read 0;" ::: "memory");
    }
}

extern "C" void kernel_launch(void* const* d_in, const int* in_sizes, int n_in,
                              void* d_out, int out_size) {
    const float* x = (const float*)d_in[0];
    float* out = (float*)d_out;
    dim3 grid(NG, NA, 16);
    detection_layer_kernel<<<grid, 256>>>(x, out);
}